// round 3
// baseline (speedup 1.0000x reference)
#include <cuda_runtime.h>
#include <cuda_bf16.h>
#include <cstdint>

// ============================================================================
// InfoNCE fused on sm_100 (plain target — no tcgen05):
//   prep:  fp32 normalize -> A = bf16(alpha*q_norm), B = bf16([d_n;q_n])
//   main:  mma.sync m16n8k16 bf16 GEMM tiles -> ex2 -> row sums (regs only)
//   reduce: loss = mean(log v_i - <q_i,d_i>/T)
// ============================================================================

#define NQ      16384
#define DD      128
#define INV_T   14.285714285714286f     // 1/0.07
#define ALPHA   20.609929155556618f     // log2(e)/0.07
#define NTILE   32                      // 128-col tiles per CTA
#define SMEM_REQ (98304 + 1024)

static __device__ __align__(256) __nv_bfloat16 g_A[(size_t)NQ * DD];
static __device__ __align__(256) __nv_bfloat16 g_B[(size_t)2 * NQ * DD];
static __device__ float g_part[(size_t)NQ * 16];
static __device__ float g_diag[NQ];
static __device__ float g_red[64];

// ------------------------------------------------------------- PTX helpers --
__device__ __forceinline__ uint32_t smem_u32(const void* p) {
    uint32_t a;
    asm("{ .reg .u64 t; cvta.to.shared.u64 t, %1; cvt.u32.u64 %0, t; }"
        : "=r"(a) : "l"(p));
    return a;
}
#define CPA16(dst, src) \
    asm volatile("cp.async.cg.shared.global [%0], [%1], 16;" :: "r"(dst), "l"(src))
#define CPA_COMMIT() asm volatile("cp.async.commit_group;" ::: "memory")
#define CPA_WAIT0()  asm volatile("cp.async.wait_group 0;" ::: "memory")
#define CPA_WAIT1()  asm volatile("cp.async.wait_group 1;" ::: "memory")

#define LDSM4(r, a) \
    asm volatile("ldmatrix.sync.aligned.m8n8.x4.shared.b16 {%0,%1,%2,%3}, [%4];" \
                 : "=r"((r)[0]), "=r"((r)[1]), "=r"((r)[2]), "=r"((r)[3]) : "r"(a))

#define MMA16816(c, a, b0, b1) \
    asm volatile("mma.sync.aligned.m16n8k16.row.col.f32.bf16.bf16.f32 " \
                 "{%0,%1,%2,%3}, {%4,%5,%6,%7}, {%8,%9}, {%0,%1,%2,%3};" \
                 : "+f"((c)[0]), "+f"((c)[1]), "+f"((c)[2]), "+f"((c)[3]) \
                 : "r"((a)[0]), "r"((a)[1]), "r"((a)[2]), "r"((a)[3]), \
                   "r"(b0), "r"(b1))

#define EX2(d, s) asm("ex2.approx.ftz.f32 %0, %1;" : "=f"(d) : "f"(s))

// SW128-style swizzle for a 128-row x 256B tile stored as blocked atoms:
// atom-col = c>>3 (two 128B halves), 16 row-atoms per atom-col.
__device__ __forceinline__ uint32_t swz(int row, int c) {
    return (uint32_t)(((row >> 3) + (c >> 3) * 16) * 1024
                      + (row & 7) * 128 + (((c & 7) ^ (row & 7)) * 16));
}

// Load one 128x128 bf16 tile (32 KB) with all 256 threads.
__device__ __forceinline__ void load_tile(uint32_t sdst, const char* gsrc, int tid) {
    #pragma unroll
    for (int t = 0; t < 8; t++) {
        int idx = tid + t * 256;           // 0..2047 16B chunks
        int row = idx >> 4, c = idx & 15;
        CPA16(sdst + swz(row, c), gsrc + (size_t)row * 256 + c * 16);
    }
}

// ------------------------------------------------------------------ kernels --
__global__ void __launch_bounds__(256) k_prep(const float* __restrict__ q,
                                              const float* __restrict__ dm) {
    int wid = threadIdx.x >> 5, lane = threadIdx.x & 31;
    int row = blockIdx.x * 8 + wid;
    float4 fq = ((const float4*)(q  + (size_t)row * DD))[lane];
    float4 fd = ((const float4*)(dm + (size_t)row * DD))[lane];
    float sq = fq.x*fq.x + fq.y*fq.y + fq.z*fq.z + fq.w*fq.w;
    float sd = fd.x*fd.x + fd.y*fd.y + fd.z*fd.z + fd.w*fd.w;
    float dt = fq.x*fd.x + fq.y*fd.y + fq.z*fd.z + fq.w*fd.w;
    #pragma unroll
    for (int o = 16; o; o >>= 1) {
        sq += __shfl_xor_sync(~0u, sq, o);
        sd += __shfl_xor_sync(~0u, sd, o);
        dt += __shfl_xor_sync(~0u, dt, o);
    }
    float rq = rsqrtf(sq), rd = rsqrtf(sd);
    float sa = rq * ALPHA;
    __nv_bfloat162* pa = (__nv_bfloat162*)(g_A + (size_t)row * DD);
    pa[lane*2]   = __floats2bfloat162_rn(fq.x*sa, fq.y*sa);
    pa[lane*2+1] = __floats2bfloat162_rn(fq.z*sa, fq.w*sa);
    __nv_bfloat162* pbd = (__nv_bfloat162*)(g_B + (size_t)row * DD);
    pbd[lane*2]   = __floats2bfloat162_rn(fd.x*rd, fd.y*rd);
    pbd[lane*2+1] = __floats2bfloat162_rn(fd.z*rd, fd.w*rd);
    __nv_bfloat162* pbq = (__nv_bfloat162*)(g_B + (size_t)(NQ + row) * DD);
    pbq[lane*2]   = __floats2bfloat162_rn(fq.x*rq, fq.y*rq);
    pbq[lane*2+1] = __floats2bfloat162_rn(fq.z*rq, fq.w*rq);
    if (lane == 0) g_diag[row] = dt * rq * rd;
}

__global__ void __launch_bounds__(256) k_main() {
    extern __shared__ char smem_raw[];
    uint32_t s0 = (smem_u32(smem_raw) + 1023u) & ~1023u;
    const uint32_t sA = s0;
    uint32_t sB[2] = { s0 + 32768u, s0 + 65536u };

    int tid = threadIdx.x, wid = tid >> 5, lane = tid & 31;
    int rb = blockIdx.x >> 3, jq = blockIdx.x & 7;
    int wm = wid >> 1, wn = wid & 1;          // 4 x 2 warp grid
    int jcta = jq * 4096;

    // ---- stage A + B0 ----
    load_tile(sA, (const char*)g_A + (size_t)rb * 128 * 256, tid);
    load_tile(sB[0], (const char*)g_B + (size_t)jcta * 256, tid);
    CPA_COMMIT();

    // ---- ldmatrix lane address precompute ----
    int r7 = lane & 7, sel = lane >> 3;
    // A: x4 tiles ordered (m-low,k-low)(m-hi,k-low)(m-low,k-hi)(m-hi,k-hi)
    int acb = sel >> 1;                        // k-half select
    uint32_t abase[2]; int ax[2];
    #pragma unroll
    for (int mi = 0; mi < 2; mi++) {
        int row = wm * 32 + mi * 16 + r7 + (sel & 1) * 8;
        abase[mi] = sA + (uint32_t)((row >> 3) * 1024 + (row & 7) * 128);
        ax[mi] = row & 7;
    }
    // B: x4 tiles ordered (n-low,k-low)(n-low,k-hi)(n-hi,k-low)(n-hi,k-hi)
    int bcb = sel & 1;
    uint32_t bbase[4]; int bx[4];
    #pragma unroll
    for (int p = 0; p < 4; p++) {
        int row = wn * 64 + p * 16 + r7 + (sel >> 1) * 8;
        bbase[p] = (uint32_t)((row >> 3) * 1024 + (row & 7) * 128);
        bx[p] = row & 7;
    }

    float rs[4] = {0.f, 0.f, 0.f, 0.f};
    int g = lane >> 2;
    int wd0 = NQ + rb * 128 + wm * 32;         // warp's diag-row window base
    int dbase = wd0 + g;                       // diag col for (mi=0, half0)
    int cbl = jcta + wn * 64 + (lane & 3) * 2; // thread col base (+t*128+ni*8)

    CPA_WAIT0();
    __syncthreads();

    for (int t = 0; t < NTILE; t++) {
        int buf = t & 1;
        if (t + 1 < NTILE)
            load_tile(sB[buf ^ 1],
                      (const char*)g_B + (size_t)(jcta + (t + 1) * 128) * 256, tid);
        CPA_COMMIT();
        CPA_WAIT1();
        __syncthreads();

        float acc[2][8][4];
        #pragma unroll
        for (int mi = 0; mi < 2; mi++)
            #pragma unroll
            for (int ni = 0; ni < 8; ni++)
                #pragma unroll
                for (int k = 0; k < 4; k++) acc[mi][ni][k] = 0.f;

        #pragma unroll
        for (int ks = 0; ks < 8; ks++) {
            uint32_t af[2][4], bf[4][4];
            {
                int c = ks * 2 + acb;
                uint32_t coff = (uint32_t)((c >> 3) * 16384);
                LDSM4(af[0], abase[0] + coff + (uint32_t)(((c & 7) ^ ax[0]) * 16));
                LDSM4(af[1], abase[1] + coff + (uint32_t)(((c & 7) ^ ax[1]) * 16));
            }
            {
                int c = ks * 2 + bcb;
                uint32_t coff = sB[buf] + (uint32_t)((c >> 3) * 16384);
                #pragma unroll
                for (int p = 0; p < 4; p++)
                    LDSM4(bf[p], coff + bbase[p] + (uint32_t)(((c & 7) ^ bx[p]) * 16));
            }
            #pragma unroll
            for (int mi = 0; mi < 2; mi++)
                #pragma unroll
                for (int ni = 0; ni < 8; ni++)
                    MMA16816(acc[mi][ni], af[mi], bf[ni >> 1][(ni & 1) * 2],
                             bf[ni >> 1][(ni & 1) * 2 + 1]);
        }

        // ---- fused epilogue: exp2 + row-sum, masking true diagonal ----
        int tc = jcta + t * 128;
        bool maydiag = (tc + wn * 64 < wd0 + 32) && (wd0 < tc + wn * 64 + 64);
        if (!maydiag) {
            #pragma unroll
            for (int mi = 0; mi < 2; mi++)
                #pragma unroll
                for (int ni = 0; ni < 8; ni++)
                    #pragma unroll
                    for (int k = 0; k < 4; k++) {
                        float e; EX2(e, acc[mi][ni][k]);
                        rs[mi * 2 + (k >> 1)] += e;
                    }
        } else {
            #pragma unroll
            for (int mi = 0; mi < 2; mi++)
                #pragma unroll
                for (int ni = 0; ni < 8; ni++)
                    #pragma unroll
                    for (int k = 0; k < 4; k++) {
                        int col = cbl + t * 128 + ni * 8 + (k & 1);
                        int dcol = dbase + mi * 16 + (k >> 1) * 8;
                        float e; EX2(e, acc[mi][ni][k]);
                        if (col != dcol) rs[mi * 2 + (k >> 1)] += e;
                    }
        }
        __syncthreads();
    }

    // reduce across the 4 lanes sharing each row
    #pragma unroll
    for (int i = 0; i < 4; i++) {
        rs[i] += __shfl_xor_sync(~0u, rs[i], 1);
        rs[i] += __shfl_xor_sync(~0u, rs[i], 2);
    }
    if ((lane & 3) == 0) {
        int rbase = rb * 128 + wm * 32 + g;
        int slot = jq * 2 + wn;
        g_part[(size_t)(rbase)      * 16 + slot] = rs[0];
        g_part[(size_t)(rbase + 8)  * 16 + slot] = rs[1];
        g_part[(size_t)(rbase + 16) * 16 + slot] = rs[2];
        g_part[(size_t)(rbase + 24) * 16 + slot] = rs[3];
    }
}

__global__ void __launch_bounds__(256) k_rows() {
    __shared__ float sm[256];
    int tid = threadIdx.x;
    int r = blockIdx.x * 256 + tid;
    const float* p = g_part + (size_t)r * 16;
    float v = 0.f;
    #pragma unroll
    for (int i = 0; i < 16; i++) v += p[i];
    sm[tid] = logf(v) - g_diag[r] * INV_T;
    __syncthreads();
    #pragma unroll
    for (int s = 128; s; s >>= 1) {
        if (tid < s) sm[tid] += sm[tid + s];
        __syncthreads();
    }
    if (tid == 0) g_red[blockIdx.x] = sm[0];
}

__global__ void k_fin(float* out) {
    int lane = threadIdx.x;
    float v = g_red[lane] + g_red[lane + 32];
    #pragma unroll
    for (int o = 16; o; o >>= 1) v += __shfl_xor_sync(~0u, v, o);
    if (lane == 0) out[0] = v * (1.0f / NQ);
}

// ------------------------------------------------------------------- launch --
extern "C" void kernel_launch(void* const* d_in, const int* in_sizes, int n_in,
                              void* d_out, int out_size) {
    const float* q  = (const float*)d_in[0];
    const float* dm = (const float*)d_in[1];
    cudaFuncSetAttribute(k_main, cudaFuncAttributeMaxDynamicSharedMemorySize, SMEM_REQ);
    k_prep<<<NQ / 8, 256>>>(q, dm);
    k_main<<<1024, 256, SMEM_REQ>>>();
    k_rows<<<64, 256>>>();
    k_fin<<<1, 32>>>((float*)d_out);
}